// round 3
// baseline (speedup 1.0000x reference)
#include <cuda_runtime.h>
#include <cuda_bf16.h>
#include <cstdint>

// ============================================================================
// PyramidResidualMoE (sm_100 legacy-tensor path; tcgen05 not available in this
// build target): out = x + baseSwiGLU(x) + expert_{argmax}(x)
// mma.sync bf16, 128x256 CTA tile, BK=32, 4-stage cp.async, ldmatrix.x4 frags,
// SwiGLU fused into gate|up epilogue (interleaved weights).
// ============================================================================

namespace cfg {
constexpr int TOK = 16384, CD = 896, HB = 1152, NEXP = 3, HEmax = 1536;
constexpr long OFS_BGU  = 0;                          // [2*HB, CD] interleaved g/u
constexpr long OFS_BD   = OFS_BGU  + 2L * HB * CD;    // [CD, HB]
constexpr long OFS_EGU0 = OFS_BD   + (long)CD * HB;
constexpr long OFS_ED0  = OFS_EGU0 + 2L * 1152 * CD;
constexpr long OFS_EGU1 = OFS_ED0  + (long)CD * 1152;
constexpr long OFS_ED1  = OFS_EGU1 + 2L * 1344 * CD;
constexpr long OFS_EGU2 = OFS_ED1  + (long)CD * 1344;
constexpr long OFS_ED2  = OFS_EGU2 + 2L * 1536 * CD;
constexpr long WTOT     = OFS_ED2  + (long)CD * 1536;
}

__device__ __nv_bfloat16 g_xb[(long)cfg::TOK * cfg::CD];
__device__ __nv_bfloat16 g_w[cfg::WTOT];
__device__ __nv_bfloat16 g_hb[(long)cfg::TOK * cfg::HB];
__device__ __nv_bfloat16 g_he[(long)cfg::TOK * cfg::HEmax];
__device__ int           g_cnt[cfg::NEXP];
__device__ int           g_idx[cfg::NEXP * cfg::TOK];
__device__ float         g_wt[cfg::TOK];

// ---------------- helpers ----------------
__device__ __forceinline__ uint32_t smem_u32(const void* p) {
    uint32_t a;
    asm("{ .reg .u64 t; cvta.to.shared.u64 t, %1; cvt.u32.u64 %0, t; }" : "=r"(a) : "l"(p));
    return a;
}
__device__ __forceinline__ void cp16(uint32_t sdst, const void* g, bool p) {
    asm volatile("cp.async.cg.shared.global [%0], [%1], 16, %2;\n"
                 :: "r"(sdst), "l"(g), "r"(p ? 16 : 0));
}
__device__ __forceinline__ void ldmx4(uint32_t r[4], uint32_t saddr) {
    asm volatile("ldmatrix.sync.aligned.m8n8.x4.shared.b16 {%0,%1,%2,%3}, [%4];"
                 : "=r"(r[0]), "=r"(r[1]), "=r"(r[2]), "=r"(r[3]) : "r"(saddr));
}
__device__ __forceinline__ void mma16816(float c[4], const uint32_t a[4],
                                         uint32_t b0, uint32_t b1) {
    asm volatile(
        "mma.sync.aligned.m16n8k16.row.col.f32.bf16.bf16.f32 "
        "{%0,%1,%2,%3}, {%4,%5,%6,%7}, {%8,%9}, {%0,%1,%2,%3};\n"
        : "+f"(c[0]), "+f"(c[1]), "+f"(c[2]), "+f"(c[3])
        : "r"(a[0]), "r"(a[1]), "r"(a[2]), "r"(a[3]), "r"(b0), "r"(b1));
}

// ============================================================================
// GEMM: C[M,NN] = A[M,K] @ B[NN,K]^T
//   BM=128 BN=256 BK=32, 512 threads (16 warps 4x4, warp tile 32x64), 4 stages.
// EPI 0: SwiGLU(cols interleaved g/u) -> hOut bf16 [M, NN/2]
// EPI 1: out = xRes + acc (fp32)
// EPI 2: out[idx[m]] += wt[idx[m]] * acc
// ============================================================================
template <bool GATHER, int EPI>
__global__ __launch_bounds__(512, 1)
void gemm_tc(const __nv_bfloat16* __restrict__ A, int lda,
             const __nv_bfloat16* __restrict__ Bw, int NN, int K,
             const int* __restrict__ cntPtr, int Mstat,
             const int* __restrict__ idx,
             __nv_bfloat16* __restrict__ hOut, int H,
             const float* __restrict__ xRes, float* __restrict__ out,
             const float* __restrict__ wt)
{
    constexpr int BM = 128, BN = 256, BK = 32, ST = 4, LDE = BK + 8; // elems/row
    constexpr int ASTE = BM * LDE;           // elems per A stage (5120)
    constexpr int BSTE = BN * LDE;           // elems per B stage (10240)
    extern __shared__ __align__(16) char smem[];
    __nv_bfloat16* As = (__nv_bfloat16*)smem;            // [ST][BM][LDE]
    __nv_bfloat16* Bs = As + (long)ST * ASTE;            // [ST][BN][LDE]
    int* ridx = (int*)(Bs + (long)ST * BSTE);            // [BM]

    const int tid = threadIdx.x, wp = tid >> 5, l = tid & 31;
    const int wm = wp >> 2, wn = wp & 3;
    const uint32_t sA = smem_u32(As), sB = smem_u32(Bs);

    const int Mdyn = cntPtr ? *cntPtr : Mstat;
    const int m0 = blockIdx.y * BM;
    if (m0 >= Mdyn) return;
    const int n0 = blockIdx.x * BN;

    if (GATHER || EPI == 2) {
        if (tid < BM) { int gm = m0 + tid; ridx[tid] = (gm < Mdyn) ? idx[gm] : 0; }
        __syncthreads();
    }

    // --- load mapping ---
    // A: 512 chunks of 16B: row=tid>>2 (0..127), c16=tid&3
    const int a_lrow = tid >> 2, a_lc = tid & 3;
    // B: 1024 chunks: thread loads 2 consecutive: row=tid>>1, c16=(tid&1)*2 +{0,1}
    const int b_lrow = tid >> 1, b_lc = (tid & 1) * 2;

    const int a_gm = m0 + a_lrow;
    const bool ap = a_gm < Mdyn;
    long a_srow = GATHER ? (ap ? (long)ridx[a_lrow] : 0L) : (ap ? (long)a_gm : 0L);
    const __nv_bfloat16* a_src = A + a_srow * lda;

    const int b_gn = n0 + b_lrow;
    const bool bp = b_gn < NN;
    const __nv_bfloat16* b_src = Bw + (long)(bp ? b_gn : 0) * K;

    auto load_stage = [&](int kc, int s) {
        uint32_t aoff = sA + (uint32_t)(s * ASTE + a_lrow * LDE) * 2 + a_lc * 16;
        cp16(aoff, a_src + kc * BK + a_lc * 8, ap);
        uint32_t boff = sB + (uint32_t)(s * BSTE + b_lrow * LDE + b_lc * 8) * 2;
        cp16(boff,      b_src + kc * BK + b_lc * 8,     bp);
        cp16(boff + 16, b_src + kc * BK + b_lc * 8 + 8, bp);
        asm volatile("cp.async.commit_group;\n" ::: "memory");
    };

    // --- ldmatrix per-lane bases ---
    const int a_mrow = wm * 32 + ((l >> 3) & 1) * 8 + (l & 7);   // + mi*16
    const int a_mk   = (l >> 4) * 8;                              // + ks*16
    const int b_mn   = wn * 64 + (l >> 4) * 8 + (l & 7);          // + p*16
    const int b_mk   = ((l >> 3) & 1) * 8;                        // + ks*16

    float c[2][8][4];
#pragma unroll
    for (int mi = 0; mi < 2; mi++)
#pragma unroll
        for (int nj = 0; nj < 8; nj++)
#pragma unroll
            for (int q = 0; q < 4; q++) c[mi][nj][q] = 0.f;

    const int KT = K / BK;
    load_stage(0, 0);
    load_stage(1, 1);
    load_stage(2, 2);

    for (int kt = 0; kt < KT; kt++) {
        const int s = kt & 3;
        const int left = KT - 1 - kt;
        if (left >= 2)      asm volatile("cp.async.wait_group 2;\n" ::: "memory");
        else if (left == 1) asm volatile("cp.async.wait_group 1;\n" ::: "memory");
        else                asm volatile("cp.async.wait_group 0;\n" ::: "memory");
        __syncthreads();
        if (kt + 3 < KT) load_stage(kt + 3, (kt + 3) & 3);

        const uint32_t aS = sA + (uint32_t)(s * ASTE) * 2;
        const uint32_t bS = sB + (uint32_t)(s * BSTE) * 2;
#pragma unroll
        for (int ks = 0; ks < 2; ks++) {
            uint32_t a[2][4];
#pragma unroll
            for (int mi = 0; mi < 2; mi++)
                ldmx4(a[mi], aS + (uint32_t)((a_mrow + mi * 16) * LDE + a_mk + ks * 16) * 2);
#pragma unroll
            for (int p = 0; p < 4; p++) {
                uint32_t b[4];
                ldmx4(b, bS + (uint32_t)((b_mn + p * 16) * LDE + b_mk + ks * 16) * 2);
                mma16816(c[0][2 * p],     a[0], b[0], b[1]);
                mma16816(c[0][2 * p + 1], a[0], b[2], b[3]);
                mma16816(c[1][2 * p],     a[1], b[0], b[1]);
                mma16816(c[1][2 * p + 1], a[1], b[2], b[3]);
            }
        }
    }

    // ---- epilogue ----
#pragma unroll
    for (int mi = 0; mi < 2; mi++) {
        const int r = m0 + wm * 32 + mi * 16 + (l >> 2);
#pragma unroll
        for (int nj = 0; nj < 8; nj++) {
            const int cl = wn * 64 + nj * 8 + (l & 3) * 2;  // local col (even)
            if (n0 + cl >= NN) continue;
            const float* cc = c[mi][nj];
            if (EPI == 0) {
                const int j = (n0 + cl) >> 1;
#pragma unroll
                for (int h = 0; h < 2; h++) {
                    int rr = r + h * 8;
                    if (rr < Mdyn) {
                        float g = cc[h * 2], u = cc[h * 2 + 1];
                        float hv = g / (1.f + __expf(-g)) * u;
                        hOut[(long)rr * H + j] = __float2bfloat16(hv);
                    }
                }
            } else if (EPI == 1) {
#pragma unroll
                for (int h = 0; h < 2; h++) {
                    int rr = r + h * 8;
                    if (rr < Mdyn) {
                        long base = (long)rr * NN + n0 + cl;
                        float2 xr = *(const float2*)&xRes[base];
                        *(float2*)&out[base] =
                            make_float2(xr.x + cc[h * 2], xr.y + cc[h * 2 + 1]);
                    }
                }
            } else {
#pragma unroll
                for (int h = 0; h < 2; h++) {
                    int rr = r + h * 8;
                    if (rr < Mdyn) {
                        int t = ridx[rr - m0];
                        float wv = wt[t];
                        long base = (long)t * NN + n0 + cl;
                        float2 o = *(float2*)&out[base];
                        o.x += wv * cc[h * 2];
                        o.y += wv * cc[h * 2 + 1];
                        *(float2*)&out[base] = o;
                    }
                }
            }
        }
    }
}

// ---------------- small kernels ----------------
__global__ void f2bf4_kernel(const float4* __restrict__ s, __nv_bfloat16* __restrict__ d, long n4) {
    long stride = (long)gridDim.x * blockDim.x;
    for (long i = blockIdx.x * (long)blockDim.x + threadIdx.x; i < n4; i += stride) {
        float4 v = s[i];
        union { __nv_bfloat162 h[2]; uint2 u; } p;
        p.h[0] = __nv_bfloat162(__float2bfloat16(v.x), __float2bfloat16(v.y));
        p.h[1] = __nv_bfloat162(__float2bfloat16(v.z), __float2bfloat16(v.w));
        *(uint2*)(d + i * 4) = p.u;
    }
}

// interleave gate/up rows: dst row 2j = gate j, 2j+1 = up j  (bf16)
__global__ void pack_gu_kernel(const float4* __restrict__ g, const float4* __restrict__ u,
                               __nv_bfloat16* __restrict__ dst, int H) {
    const int C4 = cfg::CD / 4;
    long total = (long)2 * H * C4;
    long stride = (long)gridDim.x * blockDim.x;
    for (long i = blockIdx.x * (long)blockDim.x + threadIdx.x; i < total; i += stride) {
        long r2 = i / C4; int c4 = (int)(i % C4);
        long j = r2 >> 1;
        float4 v = (r2 & 1) ? u[j * C4 + c4] : g[j * C4 + c4];
        union { __nv_bfloat162 h[2]; uint2 uu; } p;
        p.h[0] = __nv_bfloat162(__float2bfloat16(v.x), __float2bfloat16(v.y));
        p.h[1] = __nv_bfloat162(__float2bfloat16(v.z), __float2bfloat16(v.w));
        *(uint2*)(dst + r2 * cfg::CD + c4 * 4) = p.uu;
    }
}

__global__ void zero_kernel(int* cnt) { if (threadIdx.x < cfg::NEXP) cnt[threadIdx.x] = 0; }

__global__ void router_kernel(const float* __restrict__ x, const float* __restrict__ rw,
                              const float* __restrict__ bb, int* __restrict__ cnt,
                              int* __restrict__ idxArr, float* __restrict__ wt) {
    int gw = (blockIdx.x * blockDim.x + threadIdx.x) >> 5;
    int lane = threadIdx.x & 31;
    if (gw >= cfg::TOK) return;
    const float* xr = x + (long)gw * cfg::CD;
    float s0 = 0.f, s1 = 0.f, s2 = 0.f;
    for (int c = lane; c < cfg::CD; c += 32) {
        float xv = xr[c];
        s0 += xv * rw[c];
        s1 += xv * rw[cfg::CD + c];
        s2 += xv * rw[2 * cfg::CD + c];
    }
#pragma unroll
    for (int o = 16; o > 0; o >>= 1) {
        s0 += __shfl_down_sync(0xffffffffu, s0, o);
        s1 += __shfl_down_sync(0xffffffffu, s1, o);
        s2 += __shfl_down_sync(0xffffffffu, s2, o);
    }
    if (lane == 0) {
        float l0 = s0 + bb[0], l1 = s1 + bb[1], l2 = s2 + bb[2];
        int best = 0; float lb = l0;
        if (l1 > lb) { best = 1; lb = l1; }
        if (l2 > lb) { best = 2; lb = l2; }
        float p = 1.f / (1.f + expf(-lb));
        wt[gw] = p / fmaxf(p, 1e-6f);
        int pos = atomicAdd(&cnt[best], 1);
        idxArr[best * cfg::TOK + pos] = gw;
    }
}

// ============================================================================
extern "C" void kernel_launch(void* const* d_in, const int* in_sizes, int n_in,
                              void* d_out, int out_size) {
    using namespace cfg;
    (void)in_sizes; (void)n_in; (void)out_size;

    const float* x   = (const float*)d_in[0];
    const float* bgw = (const float*)d_in[1];
    const float* buw = (const float*)d_in[2];
    const float* bdw = (const float*)d_in[3];
    const float* rw  = (const float*)d_in[4];
    const float* bb  = (const float*)d_in[5];
    const float* egw[3] = {(const float*)d_in[6],  (const float*)d_in[9],  (const float*)d_in[12]};
    const float* euw[3] = {(const float*)d_in[7],  (const float*)d_in[10], (const float*)d_in[13]};
    const float* edw[3] = {(const float*)d_in[8],  (const float*)d_in[11], (const float*)d_in[14]};
    float* out = (float*)d_out;

    __nv_bfloat16 *p_xb, *p_w, *p_hb, *p_he;
    float *p_wt; int *p_cnt, *p_idx;
    cudaGetSymbolAddress((void**)&p_xb,  g_xb);
    cudaGetSymbolAddress((void**)&p_w,   g_w);
    cudaGetSymbolAddress((void**)&p_hb,  g_hb);
    cudaGetSymbolAddress((void**)&p_he,  g_he);
    cudaGetSymbolAddress((void**)&p_cnt, g_cnt);
    cudaGetSymbolAddress((void**)&p_idx, g_idx);
    cudaGetSymbolAddress((void**)&p_wt,  g_wt);

    // smem: 4*(128+256)*40*2 bytes + 512 for ridx
    constexpr size_t SMEM_SZ = 4 * (128 + 256) * 40 * 2 + 512;  // 123392
    cudaFuncSetAttribute(gemm_tc<false, 0>, cudaFuncAttributeMaxDynamicSharedMemorySize, SMEM_SZ);
    cudaFuncSetAttribute(gemm_tc<true, 0>,  cudaFuncAttributeMaxDynamicSharedMemorySize, SMEM_SZ);
    cudaFuncSetAttribute(gemm_tc<false, 1>, cudaFuncAttributeMaxDynamicSharedMemorySize, SMEM_SZ);
    cudaFuncSetAttribute(gemm_tc<false, 2>, cudaFuncAttributeMaxDynamicSharedMemorySize, SMEM_SZ);

    const int  HEs[3]    = {1152, 1344, 1536};
    const long OFS_GU[3] = {OFS_EGU0, OFS_EGU1, OFS_EGU2};
    const long OFS_D[3]  = {OFS_ED0,  OFS_ED1,  OFS_ED2};

    zero_kernel<<<1, 32>>>(p_cnt);
    f2bf4_kernel<<<2048, 256>>>((const float4*)x, p_xb, (long)TOK * CD / 4);
    pack_gu_kernel<<<1024, 256>>>((const float4*)bgw, (const float4*)buw, p_w + OFS_BGU, HB);
    f2bf4_kernel<<<512, 256>>>((const float4*)bdw, p_w + OFS_BD, (long)CD * HB / 4);
    for (int e = 0; e < 3; e++) {
        pack_gu_kernel<<<1024, 256>>>((const float4*)egw[e], (const float4*)euw[e],
                                      p_w + OFS_GU[e], HEs[e]);
        f2bf4_kernel<<<512, 256>>>((const float4*)edw[e], p_w + OFS_D[e], (long)CD * HEs[e] / 4);
    }
    router_kernel<<<TOK / 8, 256>>>(x, rw, bb, p_cnt, p_idx, p_wt);

    // base: gate|up fused-GLU, then down with residual
    gemm_tc<false, 0><<<dim3((2 * HB + 255) / 256, TOK / 128), 512, SMEM_SZ>>>(
        p_xb, CD, p_w + OFS_BGU, 2 * HB, CD, nullptr, TOK, nullptr, p_hb, HB,
        nullptr, nullptr, nullptr);
    gemm_tc<false, 1><<<dim3((CD + 255) / 256, TOK / 128), 512, SMEM_SZ>>>(
        p_hb, HB, p_w + OFS_BD, CD, HB, nullptr, TOK, nullptr, nullptr, 0,
        x, out, nullptr);

    // experts: gathered fused-GLU, then scatter-add down
    for (int e = 0; e < 3; e++) {
        int H = HEs[e];
        gemm_tc<true, 0><<<dim3((2 * H + 255) / 256, TOK / 128), 512, SMEM_SZ>>>(
            p_xb, CD, p_w + OFS_GU[e], 2 * H, CD, p_cnt + e, TOK, p_idx + e * TOK,
            p_he, H, nullptr, nullptr, nullptr);
        gemm_tc<false, 2><<<dim3((CD + 255) / 256, TOK / 128), 512, SMEM_SZ>>>(
            p_he, H, p_w + OFS_D[e], CD, H, p_cnt + e, TOK, p_idx + e * TOK,
            nullptr, 0, nullptr, out, p_wt);
    }
}

// round 5
// speedup vs baseline: 1.0142x; 1.0142x over previous
#include <cuda_runtime.h>
#include <cuda_bf16.h>
#include <cstdint>

// ============================================================================
// PyramidResidualMoE (sm_100, mma.sync path): out = x + baseSwiGLU(x) + expert_top1(x)
// R5: warp tile 64x64 (halves ldmatrix traffic/MAC), frag double-buffering,
//     single stream (no statics / no stream creation -> harness-safe),
//     launch order tuned so ncu -s 5 profiles the main GEMM.
// ============================================================================

namespace cfg {
constexpr int TOK = 16384, CD = 896, HB = 1152, NEXP = 3, HEmax = 1536;
constexpr long OFS_BGU  = 0;                          // [2*HB, CD] interleaved g/u
constexpr long OFS_BD   = OFS_BGU  + 2L * HB * CD;    // [CD, HB]
constexpr long OFS_EGU0 = OFS_BD   + (long)CD * HB;
constexpr long OFS_ED0  = OFS_EGU0 + 2L * 1152 * CD;
constexpr long OFS_EGU1 = OFS_ED0  + (long)CD * 1152;
constexpr long OFS_ED1  = OFS_EGU1 + 2L * 1344 * CD;
constexpr long OFS_EGU2 = OFS_ED1  + (long)CD * 1344;
constexpr long OFS_ED2  = OFS_EGU2 + 2L * 1536 * CD;
constexpr long WTOT     = OFS_ED2  + (long)CD * 1536;
}

__device__ __nv_bfloat16 g_xb[(long)cfg::TOK * cfg::CD];
__device__ __nv_bfloat16 g_w[cfg::WTOT];
__device__ __nv_bfloat16 g_hb[(long)cfg::TOK * cfg::HB];
__device__ __nv_bfloat16 g_he[(long)cfg::TOK * cfg::HEmax];
__device__ int           g_cnt[cfg::NEXP];
__device__ int           g_idx[cfg::NEXP * cfg::TOK];
__device__ float         g_wt[cfg::TOK];

// ---------------- helpers ----------------
__device__ __forceinline__ uint32_t smem_u32(const void* p) {
    uint32_t a;
    asm("{ .reg .u64 t; cvta.to.shared.u64 t, %1; cvt.u32.u64 %0, t; }" : "=r"(a) : "l"(p));
    return a;
}
__device__ __forceinline__ void cp16(uint32_t sdst, const void* g, bool p) {
    asm volatile("cp.async.cg.shared.global [%0], [%1], 16, %2;\n"
                 :: "r"(sdst), "l"(g), "r"(p ? 16 : 0));
}
__device__ __forceinline__ void ldmx4(uint32_t r[4], uint32_t saddr) {
    asm volatile("ldmatrix.sync.aligned.m8n8.x4.shared.b16 {%0,%1,%2,%3}, [%4];"
                 : "=r"(r[0]), "=r"(r[1]), "=r"(r[2]), "=r"(r[3]) : "r"(saddr));
}
__device__ __forceinline__ void mma16816(float c[4], const uint32_t a[4],
                                         uint32_t b0, uint32_t b1) {
    asm volatile(
        "mma.sync.aligned.m16n8k16.row.col.f32.bf16.bf16.f32 "
        "{%0,%1,%2,%3}, {%4,%5,%6,%7}, {%8,%9}, {%0,%1,%2,%3};\n"
        : "+f"(c[0]), "+f"(c[1]), "+f"(c[2]), "+f"(c[3])
        : "r"(a[0]), "r"(a[1]), "r"(a[2]), "r"(a[3]), "r"(b0), "r"(b1));
}

// ============================================================================
// GEMM: C[M,NN] = A[M,K] @ B[NN,K]^T
//   BM=256 BN=128 BK=32, 256 threads (8 warps 4x2, warp tile 64x64), 4 stages.
// EPI 0: SwiGLU(cols interleaved g/u) -> hOut bf16 [M, NN/2]
// EPI 1: out = xRes + acc (fp32)
// EPI 2: out[idx[m]] += wt[idx[m]] * acc
// ============================================================================
template <bool GATHER, int EPI>
__global__ __launch_bounds__(256, 1)
void gemm_tc(const __nv_bfloat16* __restrict__ A, int lda,
             const __nv_bfloat16* __restrict__ Bw, int NN, int K,
             const int* __restrict__ cntPtr, int Mstat,
             const int* __restrict__ idx,
             __nv_bfloat16* __restrict__ hOut, int H,
             const float* __restrict__ xRes, float* __restrict__ out,
             const float* __restrict__ wt)
{
    constexpr int BM = 256, BN = 128, BK = 32, ST = 4, LDE = BK + 8;
    constexpr int ASTE = BM * LDE;           // 10240 elems / stage
    constexpr int BSTE = BN * LDE;           // 5120 elems / stage
    extern __shared__ __align__(16) char smem[];
    __nv_bfloat16* As = (__nv_bfloat16*)smem;
    __nv_bfloat16* Bs = As + (long)ST * ASTE;
    int* ridx = (int*)(Bs + (long)ST * BSTE);

    const int tid = threadIdx.x, wp = tid >> 5, l = tid & 31;
    const int wm = wp >> 1, wn = wp & 1;      // 4 x 2 warps
    const uint32_t sA = smem_u32(As), sB = smem_u32(Bs);

    const int Mdyn = cntPtr ? *cntPtr : Mstat;
    const int m0 = blockIdx.y * BM;
    if (m0 >= Mdyn) return;
    const int n0 = blockIdx.x * BN;

    if (GATHER || EPI == 2) {
        int gm = m0 + tid;
        ridx[tid] = (gm < Mdyn) ? idx[gm] : 0;
        __syncthreads();
    }

    // ---- cp.async load mapping: 4 threads/row, chunk = (tid&3)*16B ----
    const int lrow = tid >> 2, lc = tid & 3;
    const __nv_bfloat16* a_ptr[4]; bool ap[4];
#pragma unroll
    for (int i = 0; i < 4; i++) {
        int r = lrow + 64 * i, gm = m0 + r;
        ap[i] = gm < Mdyn;
        long srow = GATHER ? (ap[i] ? (long)ridx[r] : 0L) : (ap[i] ? (long)gm : 0L);
        a_ptr[i] = A + srow * lda + lc * 8;
    }
    const __nv_bfloat16* b_ptr[2];
#pragma unroll
    for (int i = 0; i < 2; i++) {
        int gn = n0 + lrow + 64 * i;
        b_ptr[i] = Bw + (long)gn * K + lc * 8;
    }
    uint32_t a_soff[4], b_soff[2];
#pragma unroll
    for (int i = 0; i < 4; i++) a_soff[i] = sA + (uint32_t)((lrow + 64 * i) * LDE) * 2 + lc * 16;
#pragma unroll
    for (int i = 0; i < 2; i++) b_soff[i] = sB + (uint32_t)((lrow + 64 * i) * LDE) * 2 + lc * 16;

    auto load_stage = [&](int kc, int s) {
#pragma unroll
        for (int i = 0; i < 4; i++)
            cp16(a_soff[i] + (uint32_t)(s * ASTE) * 2, a_ptr[i] + kc * BK, ap[i]);
#pragma unroll
        for (int i = 0; i < 2; i++)
            cp16(b_soff[i] + (uint32_t)(s * BSTE) * 2, b_ptr[i] + kc * BK, true);
        asm volatile("cp.async.commit_group;\n" ::: "memory");
    };

    // ---- ldmatrix per-lane bases ----
    const int lrA = (l & 7) + ((l >> 3) & 1) * 8;  // row within 16
    const int akb = (l >> 4) * 8;                   // k within 16
    const int lrB = (l >> 4) * 8 + (l & 7);         // col within 16
    const int bkb = ((l >> 3) & 1) * 8;

    float c[4][8][4];
#pragma unroll
    for (int mi = 0; mi < 4; mi++)
#pragma unroll
        for (int nj = 0; nj < 8; nj++)
#pragma unroll
            for (int q = 0; q < 4; q++) c[mi][nj][q] = 0.f;

    auto ldfrags = [&](uint32_t aS, uint32_t bS, int ks, uint32_t fa[4][4], uint32_t fb[4][4]) {
#pragma unroll
        for (int mi = 0; mi < 4; mi++)
            ldmx4(fa[mi], aS + (uint32_t)((wm * 64 + mi * 16 + lrA) * LDE + akb + ks * 16) * 2);
#pragma unroll
        for (int p = 0; p < 4; p++)
            ldmx4(fb[p], bS + (uint32_t)((wn * 64 + p * 16 + lrB) * LDE + bkb + ks * 16) * 2);
    };

    const int KT = K / BK;
    load_stage(0, 0);
    load_stage(1, 1);
    load_stage(2, 2);

    uint32_t fa[2][4][4], fb[2][4][4];

    for (int kt = 0; kt < KT; kt++) {
        const int s = kt & 3;
        const int left = KT - 1 - kt;
        if (left >= 2)      asm volatile("cp.async.wait_group 2;\n" ::: "memory");
        else if (left == 1) asm volatile("cp.async.wait_group 1;\n" ::: "memory");
        else                asm volatile("cp.async.wait_group 0;\n" ::: "memory");
        __syncthreads();
        if (kt + 3 < KT) load_stage(kt + 3, (kt + 3) & 3);

        const uint32_t aS = sA + (uint32_t)(s * ASTE) * 2;
        const uint32_t bS = sB + (uint32_t)(s * BSTE) * 2;
        ldfrags(aS, bS, 0, fa[0], fb[0]);
#pragma unroll
        for (int ks = 0; ks < 2; ks++) {
            if (ks == 0) ldfrags(aS, bS, 1, fa[1], fb[1]);   // prefetch overlaps MMAs
            uint32_t (*a4)[4] = fa[ks], (*b4)[4] = fb[ks];
#pragma unroll
            for (int p = 0; p < 4; p++) {
#pragma unroll
                for (int mi = 0; mi < 4; mi++) {
                    mma16816(c[mi][2 * p],     a4[mi], b4[p][0], b4[p][1]);
                    mma16816(c[mi][2 * p + 1], a4[mi], b4[p][2], b4[p][3]);
                }
            }
        }
    }

    // ---- epilogue ----
#pragma unroll
    for (int mi = 0; mi < 4; mi++) {
        const int r = m0 + wm * 64 + mi * 16 + (l >> 2);
#pragma unroll
        for (int nj = 0; nj < 8; nj++) {
            const int cl = wn * 64 + nj * 8 + (l & 3) * 2;
            const float* cc = c[mi][nj];
            if (EPI == 0) {
                const int j = (n0 + cl) >> 1;
#pragma unroll
                for (int h = 0; h < 2; h++) {
                    int rr = r + h * 8;
                    if (rr < Mdyn) {
                        float g = cc[h * 2], u = cc[h * 2 + 1];
                        float hv = g / (1.f + __expf(-g)) * u;
                        hOut[(long)rr * H + j] = __float2bfloat16(hv);
                    }
                }
            } else if (EPI == 1) {
#pragma unroll
                for (int h = 0; h < 2; h++) {
                    int rr = r + h * 8;
                    if (rr < Mdyn) {
                        long base = (long)rr * NN + n0 + cl;
                        float2 xr = *(const float2*)&xRes[base];
                        *(float2*)&out[base] =
                            make_float2(xr.x + cc[h * 2], xr.y + cc[h * 2 + 1]);
                    }
                }
            } else {
#pragma unroll
                for (int h = 0; h < 2; h++) {
                    int rr = r + h * 8;
                    if (rr < Mdyn) {
                        int t = ridx[rr - m0];
                        float wv = wt[t];
                        long base = (long)t * NN + n0 + cl;
                        float2 o = *(float2*)&out[base];
                        o.x += wv * cc[h * 2];
                        o.y += wv * cc[h * 2 + 1];
                        *(float2*)&out[base] = o;
                    }
                }
            }
        }
    }
}

// ---------------- small kernels ----------------
__global__ void f2bf4_kernel(const float4* __restrict__ s, __nv_bfloat16* __restrict__ d, long n4) {
    long stride = (long)gridDim.x * blockDim.x;
    for (long i = blockIdx.x * (long)blockDim.x + threadIdx.x; i < n4; i += stride) {
        float4 v = s[i];
        union { __nv_bfloat162 h[2]; uint2 u; } p;
        p.h[0] = __nv_bfloat162(__float2bfloat16(v.x), __float2bfloat16(v.y));
        p.h[1] = __nv_bfloat162(__float2bfloat16(v.z), __float2bfloat16(v.w));
        *(uint2*)(d + i * 4) = p.u;
    }
}

__global__ void pack_gu_kernel(const float4* __restrict__ g, const float4* __restrict__ u,
                               __nv_bfloat16* __restrict__ dst, int H) {
    const int C4 = cfg::CD / 4;
    long total = (long)2 * H * C4;
    long stride = (long)gridDim.x * blockDim.x;
    for (long i = blockIdx.x * (long)blockDim.x + threadIdx.x; i < total; i += stride) {
        long r2 = i / C4; int c4 = (int)(i % C4);
        long j = r2 >> 1;
        float4 v = (r2 & 1) ? u[j * C4 + c4] : g[j * C4 + c4];
        union { __nv_bfloat162 h[2]; uint2 uu; } p;
        p.h[0] = __nv_bfloat162(__float2bfloat16(v.x), __float2bfloat16(v.y));
        p.h[1] = __nv_bfloat162(__float2bfloat16(v.z), __float2bfloat16(v.w));
        *(uint2*)(dst + r2 * cfg::CD + c4 * 4) = p.uu;
    }
}

__global__ void zero_kernel(int* cnt) { if (threadIdx.x < cfg::NEXP) cnt[threadIdx.x] = 0; }

__global__ void router_kernel(const float* __restrict__ x, const float* __restrict__ rw,
                              const float* __restrict__ bb, int* __restrict__ cnt,
                              int* __restrict__ idxArr, float* __restrict__ wt) {
    int gw = (blockIdx.x * blockDim.x + threadIdx.x) >> 5;
    int lane = threadIdx.x & 31;
    if (gw >= cfg::TOK) return;
    const float* xr = x + (long)gw * cfg::CD;
    float s0 = 0.f, s1 = 0.f, s2 = 0.f;
    for (int c = lane; c < cfg::CD; c += 32) {
        float xv = xr[c];
        s0 += xv * rw[c];
        s1 += xv * rw[cfg::CD + c];
        s2 += xv * rw[2 * cfg::CD + c];
    }
#pragma unroll
    for (int o = 16; o > 0; o >>= 1) {
        s0 += __shfl_down_sync(0xffffffffu, s0, o);
        s1 += __shfl_down_sync(0xffffffffu, s1, o);
        s2 += __shfl_down_sync(0xffffffffu, s2, o);
    }
    if (lane == 0) {
        float l0 = s0 + bb[0], l1 = s1 + bb[1], l2 = s2 + bb[2];
        int best = 0; float lb = l0;
        if (l1 > lb) { best = 1; lb = l1; }
        if (l2 > lb) { best = 2; lb = l2; }
        float p = 1.f / (1.f + expf(-lb));
        wt[gw] = p / fmaxf(p, 1e-6f);
        int pos = atomicAdd(&cnt[best], 1);
        idxArr[best * cfg::TOK + pos] = gw;
    }
}

// ============================================================================
extern "C" void kernel_launch(void* const* d_in, const int* in_sizes, int n_in,
                              void* d_out, int out_size) {
    using namespace cfg;
    (void)in_sizes; (void)n_in; (void)out_size;

    const float* x   = (const float*)d_in[0];
    const float* bgw = (const float*)d_in[1];
    const float* buw = (const float*)d_in[2];
    const float* bdw = (const float*)d_in[3];
    const float* rw  = (const float*)d_in[4];
    const float* bb  = (const float*)d_in[5];
    const float* egw[3] = {(const float*)d_in[6],  (const float*)d_in[9],  (const float*)d_in[12]};
    const float* euw[3] = {(const float*)d_in[7],  (const float*)d_in[10], (const float*)d_in[13]};
    const float* edw[3] = {(const float*)d_in[8],  (const float*)d_in[11], (const float*)d_in[14]};
    float* out = (float*)d_out;

    __nv_bfloat16 *p_xb, *p_w, *p_hb, *p_he;
    float *p_wt; int *p_cnt, *p_idx;
    cudaGetSymbolAddress((void**)&p_xb,  g_xb);
    cudaGetSymbolAddress((void**)&p_w,   g_w);
    cudaGetSymbolAddress((void**)&p_hb,  g_hb);
    cudaGetSymbolAddress((void**)&p_he,  g_he);
    cudaGetSymbolAddress((void**)&p_cnt, g_cnt);
    cudaGetSymbolAddress((void**)&p_idx, g_idx);
    cudaGetSymbolAddress((void**)&p_wt,  g_wt);

    constexpr size_t SMEM_SZ = 4 * (256 + 128) * 40 * 2 + 1024;  // 123904
    cudaFuncSetAttribute(gemm_tc<false, 0>, cudaFuncAttributeMaxDynamicSharedMemorySize, SMEM_SZ);
    cudaFuncSetAttribute(gemm_tc<true, 0>,  cudaFuncAttributeMaxDynamicSharedMemorySize, SMEM_SZ);
    cudaFuncSetAttribute(gemm_tc<false, 1>, cudaFuncAttributeMaxDynamicSharedMemorySize, SMEM_SZ);
    cudaFuncSetAttribute(gemm_tc<false, 2>, cudaFuncAttributeMaxDynamicSharedMemorySize, SMEM_SZ);

    const int  HEs[3]    = {1152, 1344, 1536};
    const long OFS_GU[3] = {OFS_EGU0, OFS_EGU1, OFS_EGU2};
    const long OFS_D[3]  = {OFS_ED0,  OFS_ED1,  OFS_ED2};

    // launches 1..5, then base gate|up GEMM as launch #6 (ncu -s 5 -c 1 target)
    zero_kernel<<<1, 32>>>(p_cnt);                                            // 1
    f2bf4_kernel<<<2048, 256>>>((const float4*)x, p_xb, (long)TOK * CD / 4);  // 2
    pack_gu_kernel<<<1024, 256>>>((const float4*)bgw, (const float4*)buw,
                                  p_w + OFS_BGU, HB);                         // 3
    f2bf4_kernel<<<512, 256>>>((const float4*)bdw, p_w + OFS_BD,
                               (long)CD * HB / 4);                            // 4
    router_kernel<<<TOK / 8, 256>>>(x, rw, bb, p_cnt, p_idx, p_wt);           // 5

    // base gate|up  (launch #6)
    gemm_tc<false, 0><<<dim3(2 * HB / 128, TOK / 256), 256, SMEM_SZ>>>(
        p_xb, CD, p_w + OFS_BGU, 2 * HB, CD, nullptr, TOK, nullptr, p_hb, HB,
        nullptr, nullptr, nullptr);
    // base down with residual
    gemm_tc<false, 1><<<dim3(CD / 128, TOK / 256), 256, SMEM_SZ>>>(
        p_hb, HB, p_w + OFS_BD, CD, HB, nullptr, TOK, nullptr, nullptr, 0,
        x, out, nullptr);

    // expert weight packing, then expert chains (single stream)
    for (int e = 0; e < 3; e++) {
        int H = HEs[e];
        pack_gu_kernel<<<512, 256>>>((const float4*)egw[e], (const float4*)euw[e],
                                     p_w + OFS_GU[e], H);
        f2bf4_kernel<<<256, 256>>>((const float4*)edw[e], p_w + OFS_D[e],
                                   (long)CD * H / 4);
        gemm_tc<true, 0><<<dim3(2 * H / 128, TOK / 256), 256, SMEM_SZ>>>(
            p_xb, CD, p_w + OFS_GU[e], 2 * H, CD, p_cnt + e, TOK, p_idx + e * TOK,
            p_he, H, nullptr, nullptr, nullptr);
        gemm_tc<false, 2><<<dim3(CD / 128, TOK / 256), 256, SMEM_SZ>>>(
            p_he, H, p_w + OFS_D[e], CD, H, p_cnt + e, TOK, p_idx + e * TOK,
            nullptr, 0, nullptr, out, p_wt);
    }
}